// round 7
// baseline (speedup 1.0000x reference)
#include <cuda_runtime.h>

// out = segment_sum(x, batch); batch sorted int32, N=1e6, C=128, G=10000.
// softmax over size-1 axis == 1.0 -> W/b dead inputs.
// R7: single kernel. Warp-cooperative 32-ary lower_bound (4 dependent probe
// rounds, ballot-based; warp0 -> bound(g), warp1 -> bound(g+1), top rounds
// L2-hot since all blocks probe the same addresses), then the R6 streaming
// loop (LDG.128, dual accumulators), smem reduce, direct store.

#define C 128
#define C4 (C / 4)
#define WARPS 4

// First index i in [0,n) with batch[i] >= target (warp-collective, all lanes
// return the same value). Invariant: batch[lo] < target <= batch[hi]
// (virtual batch[-1] = -inf, batch[n] = +inf).
__device__ __forceinline__ int lower_bound_warp(const int* __restrict__ batch,
                                                int n, int target, int lane)
{
    int lo = -1, hi = n;
    while (hi - lo > 1) {
        int span = hi - lo;
        int off = (int)(((long long)span * (lane + 1)) / 33);   // in [0, span)
        int p = lo + off;
        bool valid = (off > 0) && (p < hi);
        bool pred = valid && (__ldg(&batch[p]) >= target);
        unsigned bp = __ballot_sync(0xffffffffu, pred);
        unsigned bn = __ballot_sync(0xffffffffu, valid && !pred);
        if (bp) {   // smallest probed p with pred -> new hi
            int fl = __ffs(bp) - 1;
            hi = lo + (int)(((long long)span * (fl + 1)) / 33);
        }
        if (bn) {   // largest probed p without pred -> new lo
            int ll = 31 - __clz(bn);
            lo = lo + (int)(((long long)span * (ll + 1)) / 33);
        }
    }
    return hi;
}

__global__ __launch_bounds__(WARPS * 32) void seg_sum_kernel(
    const float4* __restrict__ x4,
    const int* __restrict__ batch,
    float4* __restrict__ out4,
    int n)
{
    const int g    = blockIdx.x;
    const int warp = threadIdx.x >> 5;
    const int lane = threadIdx.x & 31;       // owns channels [4*lane, 4*lane+4)

    __shared__ int s_bounds[2];
    if (warp == 0) {
        int s = lower_bound_warp(batch, n, g, lane);
        if (lane == 0) s_bounds[0] = s;
    } else if (warp == 1) {
        int e = lower_bound_warp(batch, n, g + 1, lane);
        if (lane == 0) s_bounds[1] = e;
    }
    __syncthreads();
    const int s = s_bounds[0];
    const int e = s_bounds[1];

    // dual accumulators; each warp strides rows by WARPS
    float4 a0 = make_float4(0.f, 0.f, 0.f, 0.f);
    float4 a1 = make_float4(0.f, 0.f, 0.f, 0.f);

    int r = s + warp;
    for (; r + WARPS < e; r += 2 * WARPS) {
        float4 v0 = __ldg(&x4[(size_t)r * C4 + lane]);
        float4 v1 = __ldg(&x4[(size_t)(r + WARPS) * C4 + lane]);
        a0.x += v0.x; a0.y += v0.y; a0.z += v0.z; a0.w += v0.w;
        a1.x += v1.x; a1.y += v1.y; a1.z += v1.z; a1.w += v1.w;
    }
    if (r < e) {
        float4 v = __ldg(&x4[(size_t)r * C4 + lane]);
        a0.x += v.x; a0.y += v.y; a0.z += v.z; a0.w += v.w;
    }
    a0.x += a1.x; a0.y += a1.y; a0.z += a1.z; a0.w += a1.w;

    __shared__ float4 sacc[WARPS][C4];
    sacc[warp][lane] = a0;
    __syncthreads();

    if (warp == 0) {
        float4 a = sacc[0][lane], b = sacc[1][lane],
               c = sacc[2][lane], d = sacc[3][lane];
        a.x += b.x + c.x + d.x;
        a.y += b.y + c.y + d.y;
        a.z += b.z + c.z + d.z;
        a.w += b.w + c.w + d.w;
        out4[(size_t)g * C4 + lane] = a;     // direct store; zeros if empty
    }
}

extern "C" void kernel_launch(void* const* d_in, const int* in_sizes, int n_in,
                              void* d_out, int out_size)
{
    const float4* x4    = (const float4*)d_in[0];
    const int*    batch = (const int*)d_in[1];
    // d_in[2] = W, d_in[3] = b : dead (softmax over size-1 axis)
    float4* out4 = (float4*)d_out;

    const int n    = in_sizes[0] / C;        // rows of x
    const int nseg = out_size / C;           // segments (10000)

    seg_sum_kernel<<<nseg, WARPS * 32>>>(x4, batch, out4, n);
}

// round 8
// speedup vs baseline: 1.0443x; 1.0443x over previous
#include <cuda_runtime.h>

// out = segment_sum(x, batch); batch sorted int32, N=1e6, C=128, G=10000.
// softmax over size-1 axis == 1.0 -> W/b dead inputs.
// R8: identical compute to R6 (best: offsets pass + block-per-segment
// streaming), but the two kernels are linked with Programmatic Dependent
// Launch: seg_sum is launched with ProgrammaticStreamSerialization and calls
// cudaGridDependencySynchronize() before reading g_start, overlapping its
// launch/scheduling with the offsets kernel's execution.

#define C 128
#define C4 (C / 4)
#define WARPS 4
#define MAX_SEG 10000

__device__ int g_start[MAX_SEG + 1];   // start[g] = first row with batch[i] >= g

// Vectorized boundary scatter: thread i handles batch[4i .. 4i+3].
__global__ void offsets_kernel(const int4* __restrict__ batch4,
                               const int* __restrict__ batch,
                               int n4, int n, int nseg) {
    int i = blockIdx.x * blockDim.x + threadIdx.x;
    if (i >= n4) return;
    int4 v = __ldg(&batch4[i]);
    int prev = (i == 0) ? -1 : __ldg(&batch[4 * i - 1]);   // L1 hit (neighbor)
    if (v.x != prev) for (int g = prev + 1; g <= v.x; ++g) g_start[g] = 4 * i;
    if (v.y != v.x)  for (int g = v.x + 1;  g <= v.y; ++g) g_start[g] = 4 * i + 1;
    if (v.z != v.y)  for (int g = v.y + 1;  g <= v.z; ++g) g_start[g] = 4 * i + 2;
    if (v.w != v.z)  for (int g = v.z + 1;  g <= v.w; ++g) g_start[g] = 4 * i + 3;
    if (4 * i + 4 >= n)                                    // last thread
        for (int g = v.w + 1; g <= nseg; ++g) g_start[g] = n;
}

__global__ __launch_bounds__(WARPS * 32) void seg_sum_kernel(
    const float4* __restrict__ x4,
    float4* __restrict__ out4)
{
    const int g    = blockIdx.x;
    const int warp = threadIdx.x >> 5;
    const int lane = threadIdx.x & 31;       // owns channels [4*lane, 4*lane+4)

    // PDL: wait for offsets_kernel's grid before consuming g_start.
    cudaGridDependencySynchronize();

    const int s = g_start[g];
    const int e = g_start[g + 1];

    // dual accumulators: halve the per-component FADD dependency chain
    float4 a0 = make_float4(0.f, 0.f, 0.f, 0.f);
    float4 a1 = make_float4(0.f, 0.f, 0.f, 0.f);

    int r = s + warp;
    for (; r + WARPS < e; r += 2 * WARPS) {
        float4 v0 = __ldg(&x4[(size_t)r * C4 + lane]);
        float4 v1 = __ldg(&x4[(size_t)(r + WARPS) * C4 + lane]);
        a0.x += v0.x; a0.y += v0.y; a0.z += v0.z; a0.w += v0.w;
        a1.x += v1.x; a1.y += v1.y; a1.z += v1.z; a1.w += v1.w;
    }
    if (r < e) {
        float4 v = __ldg(&x4[(size_t)r * C4 + lane]);
        a0.x += v.x; a0.y += v.y; a0.z += v.z; a0.w += v.w;
    }
    a0.x += a1.x; a0.y += a1.y; a0.z += a1.z; a0.w += a1.w;

    __shared__ float4 sacc[WARPS][C4];
    sacc[warp][lane] = a0;
    __syncthreads();

    if (warp == 0) {
        float4 a = sacc[0][lane], b = sacc[1][lane],
               c = sacc[2][lane], d = sacc[3][lane];
        a.x += b.x + c.x + d.x;
        a.y += b.y + c.y + d.y;
        a.z += b.z + c.z + d.z;
        a.w += b.w + c.w + d.w;
        out4[(size_t)g * C4 + lane] = a;     // direct store; zeros if empty
    }
}

extern "C" void kernel_launch(void* const* d_in, const int* in_sizes, int n_in,
                              void* d_out, int out_size)
{
    const float4* x4    = (const float4*)d_in[0];
    const int*    batch = (const int*)d_in[1];
    // d_in[2] = W, d_in[3] = b : dead (softmax over size-1 axis)
    float4* out4 = (float4*)d_out;

    const int n    = in_sizes[0] / C;        // rows of x (1e6, divisible by 4)
    const int nseg = out_size / C;           // segments (10000)
    const int n4   = n / 4;

    offsets_kernel<<<(n4 + 255) / 256, 256>>>((const int4*)batch, batch,
                                              n4, n, nseg);

    // seg_sum with Programmatic Dependent Launch so its scheduling overlaps
    // the offsets kernel's execution.
    cudaLaunchConfig_t cfg = {};
    cfg.gridDim  = dim3(nseg, 1, 1);
    cfg.blockDim = dim3(WARPS * 32, 1, 1);
    cfg.dynamicSmemBytes = 0;
    cfg.stream = 0;
    cudaLaunchAttribute attrs[1];
    attrs[0].id = cudaLaunchAttributeProgrammaticStreamSerialization;
    attrs[0].val.programmaticStreamSerializationAllowed = 1;
    cfg.attrs = attrs;
    cfg.numAttrs = 1;
    cudaLaunchKernelEx(&cfg, seg_sum_kernel, x4, out4);
}